// round 14
// baseline (speedup 1.0000x reference)
#include <cuda_runtime.h>
#include <math.h>

// Problem constants (fixed by the reference's setup_inputs)
#define Bc 2
#define Vc 3
#define Cc 32
#define Dc 32
#define Hc 96
#define Wc 128
#define HWc (Hc * Wc)            // 12288
#define VOLc (Bc * Dc * Hc * Wc) // 786432
#define BHWc (Bc * Hc * Wc)      // 24576
#define NSRC (Vc - 1)            // 2 source views
#define NG 8                     // channel groups of 4

typedef unsigned long long u64;

// Scratch (static device globals — no allocation)
__device__ float4 g_feat4[Bc * Vc * NG * HWc]; // channel-grouped features ~9.4MB
__device__ float g_s[9 * VOLc];                // x-folded 9-tap partials (~28 MB)
__device__ float g_xform[Bc * NSRC * 12];      // rot(9) + trans(3) per (b, src view)
__device__ ulonglong2 g_swp[27 * 8];           // packed weights staging (device)

// Constant bank: packed weights [tap][pair-pair] (3456 B)
__constant__ ulonglong2 c_sw[27 * 8];

// ---------------------------------------------------------------------------
// f32x2 packed helpers (Blackwell)
// ---------------------------------------------------------------------------
__device__ __forceinline__ u64 pk2(float a, float b) {
    u64 r; asm("mov.b64 %0, {%1,%2};" : "=l"(r) : "f"(a), "f"(b)); return r;
}
__device__ __forceinline__ u64 fma2_(u64 a, u64 b, u64 c) {
    u64 d; asm("fma.rn.f32x2 %0, %1, %2, %3;" : "=l"(d) : "l"(a), "l"(b), "l"(c)); return d;
}
__device__ __forceinline__ u64 mul2_(u64 a, u64 b) {
    u64 d; asm("mul.rn.f32x2 %0, %1, %2;" : "=l"(d) : "l"(a), "l"(b)); return d;
}
__device__ __forceinline__ u64 add2_(u64 a, u64 b) {
    u64 d; asm("add.rn.f32x2 %0, %1, %2;" : "=l"(d) : "l"(a), "l"(b)); return d;
}
__device__ __forceinline__ float hadd2(u64 a) {
    float x, y; asm("mov.b64 {%0,%1}, %2;" : "=f"(x), "=f"(y) : "l"(a)); return x + y;
}
__device__ __forceinline__ void unpk2(u64 a, float& x, float& y) {
    asm("mov.b64 {%0,%1}, %2;" : "=f"(x), "=f"(y) : "l"(a));
}
#define THIRD2 0x3EAAAAAB3EAAAAABULL
#define NEG2MASK 0x8000000080000000ULL

// ---------------------------------------------------------------------------
// Fused setup+prep: warp 0 composes/inverts projections; warps 1..7 pack the
// conv weights into the [tap][pair] f32x2 staging buffer for the const copy.
// ---------------------------------------------------------------------------
__device__ void compose_mat(const float* pm, int b, int v, float P[16]) {
    const float* E = pm + (((b * Vc + v) * 2 + 0) * 16);
    const float* K = pm + (((b * Vc + v) * 2 + 1) * 16);
#pragma unroll
    for (int i = 0; i < 16; i++) P[i] = E[i];
#pragma unroll
    for (int i = 0; i < 3; i++)
#pragma unroll
        for (int j = 0; j < 4; j++)
            P[i * 4 + j] = K[i * 4 + 0] * E[0 * 4 + j] +
                           K[i * 4 + 1] * E[1 * 4 + j] +
                           K[i * 4 + 2] * E[2 * 4 + j];
}

__device__ void inv4(const float A[16], float R[16]) {
    float M[4][8];
    for (int i = 0; i < 4; i++) {
        for (int j = 0; j < 4; j++) {
            M[i][j] = A[i * 4 + j];
            M[i][4 + j] = (i == j) ? 1.f : 0.f;
        }
    }
    for (int col = 0; col < 4; col++) {
        int piv = col;
        float best = fabsf(M[col][col]);
        for (int r = col + 1; r < 4; r++) {
            float a = fabsf(M[r][col]);
            if (a > best) { best = a; piv = r; }
        }
        if (piv != col) {
            for (int j = 0; j < 8; j++) {
                float t = M[col][j]; M[col][j] = M[piv][j]; M[piv][j] = t;
            }
        }
        float p = 1.f / M[col][col];
        for (int j = 0; j < 8; j++) M[col][j] *= p;
        for (int r = 0; r < 4; r++) {
            if (r == col) continue;
            float f = M[r][col];
            for (int j = 0; j < 8; j++) M[r][j] -= f * M[col][j];
        }
    }
    for (int i = 0; i < 4; i++)
        for (int j = 0; j < 4; j++)
            R[i * 4 + j] = M[i][4 + j];
}

__global__ void setup_kernel(const float* __restrict__ pm,
                             const float* __restrict__ w_reg) {
    int tid = threadIdx.x;  // 512 threads
    if (tid < Bc * NSRC) {
        int t = tid;
        int b = t / NSRC;
        int v = (t % NSRC) + 1;
        float refP[16], srcP[16], invR[16], proj[16];
        compose_mat(pm, b, 0, refP);
        compose_mat(pm, b, v, srcP);
        inv4(refP, invR);
        for (int i = 0; i < 4; i++)
            for (int j = 0; j < 4; j++) {
                float s = 0.f;
                for (int k = 0; k < 4; k++) s += srcP[i * 4 + k] * invR[k * 4 + j];
                proj[i * 4 + j] = s;
            }
        float* X = g_xform + t * 12;
        X[0] = proj[0];  X[1] = proj[1];  X[2] = proj[2];
        X[3] = proj[4];  X[4] = proj[5];  X[5] = proj[6];
        X[6] = proj[8];  X[7] = proj[9];  X[8] = proj[10];
        X[9] = proj[3];  X[10] = proj[7]; X[11] = proj[11];
    }
    int i = tid - 32;  // weight packing on threads 32..463
    if (i >= 0 && i < 27 * 16) {
        int t = i >> 4, p = i & 15;
        u64* sw = (u64*)g_swp;
        sw[t * 16 + p] = pk2(w_reg[(2 * p) * 27 + t], w_reg[(2 * p + 1) * 27 + t]);
    }
}

// ---------------------------------------------------------------------------
// Repack features: (B,V,C,H,W) -> (B,V, C/4, H, W)[float4 over 4 channels]
// ---------------------------------------------------------------------------
__global__ __launch_bounds__(256) void repack_kernel(const float* __restrict__ feat) {
    __shared__ float tile[32][33];
    int bv = blockIdx.y;
    int pix0 = blockIdx.x * 32;
    int tx = threadIdx.x, ty = threadIdx.y; // 32 x 8
    const float* src = feat + (size_t)bv * Cc * HWc;
#pragma unroll
    for (int i = 0; i < 4; i++) {
        int c = ty + i * 8;
        tile[c][tx] = src[(size_t)c * HWc + pix0 + tx];
    }
    __syncthreads();
    float4 v;
    v.x = tile[4 * ty + 0][tx];
    v.y = tile[4 * ty + 1][tx];
    v.z = tile[4 * ty + 2][tx];
    v.w = tile[4 * ty + 3][tx];
    g_feat4[((size_t)bv * NG + ty) * HWc + pix0 + tx] = v;
}

// ---------------------------------------------------------------------------
// build_s: proven r13 version — trimmed regs, weights on the constant port.
// ---------------------------------------------------------------------------
__global__ __launch_bounds__(128, 4) void build_s_kernel(
    const float* __restrict__ depth_values)
{
    __shared__ u64 su[18][130];   // dx0 taps [0..8], dx2 taps [9..17], depth-pair packed

    int x = threadIdx.x;
    if (x < 18) { su[x][0] = 0ULL; su[x][129] = 0ULL; }
    __syncthreads();

    int row = blockIdx.x;                 // (b*(D/2) + d2)*H + h
    int h = row % Hc;
    int d2 = (row / Hc) & (Dc / 2 - 1);
    int b = row / (Hc * Dc / 2);
    int idx0 = ((b * Dc + 2 * d2) * Hc + h) * Wc + x;
    int idx1 = idx0 + HWc;

    float dep[2];
    dep[0] = depth_values[idx0];
    dep[1] = depth_values[idx1];

    // Warp coords per (depth, view): scalar weights + packed gather offsets
    float wtf[2][NSRC][4];
    unsigned int offp[2][NSRC][2]; // two 16-bit pixel offsets per reg
#pragma unroll
    for (int di = 0; di < 2; di++) {
#pragma unroll
        for (int s = 0; s < NSRC; s++) {
            const float* X = g_xform + (b * NSRC + s) * 12;
            float fx = (float)x, fy = (float)h;
            float Xx = (X[0] * fx + X[1] * fy + X[2]) * dep[di] + X[9];
            float Yy = (X[3] * fx + X[4] * fy + X[5]) * dep[di] + X[10];
            float Zz = (X[6] * fx + X[7] * fy + X[8]) * dep[di] + X[11];
            float iz = 1.f / Zz;
            float px = Xx * iz, py = Yy * iz;
            float x0 = floorf(px), y0 = floorf(py);
            float ax = px - x0, ay = py - y0;
            unsigned int o[4];
#pragma unroll
            for (int k = 0; k < 4; k++) {
                int dx = k & 1, dy = k >> 1;
                float xi = x0 + (float)dx, yi = y0 + (float)dy;
                float wg = (dx ? ax : 1.f - ax) * (dy ? ay : 1.f - ay);
                bool valid = (xi >= 0.f) && (xi <= (float)(Wc - 1)) &&
                             (yi >= 0.f) && (yi <= (float)(Hc - 1));
                wtf[di][s][k] = valid ? wg : 0.f;
                int xc = min(max((int)xi, 0), Wc - 1);
                int yc = min(max((int)yi, 0), Hc - 1);
                o[k] = (unsigned int)(yc * Wc + xc);
            }
            offp[di][s][0] = o[0] | (o[1] << 16);
            offp[di][s][1] = o[2] | (o[3] << 16);
        }
    }

    int pix = h * Wc + x;
    const float4* fr = g_feat4 + (size_t)(b * Vc + 0) * (NG * HWc) + pix;
    const float4* f1 = g_feat4 + (size_t)(b * Vc + 1) * (NG * HWc);
    const float4* f2 = g_feat4 + (size_t)(b * Vc + 2) * (NG * HWc);

    // Phase A: variance, channel-pair packed, per depth
    u64 var[16][2]; // [channel pair][depth]
#pragma unroll
    for (int q = 0; q < NG; q++) {
        float4 r4 = fr[q * HWc];
        u64 r01 = pk2(r4.x, r4.y), r23 = pk2(r4.z, r4.w);
        const float4* p1 = f1 + q * HWc;
        const float4* p2 = f2 + q * HWc;
#pragma unroll
        for (int di = 0; di < 2; di++) {
            unsigned int pa0 = offp[di][0][0], pa1 = offp[di][0][1];
            unsigned int pb0 = offp[di][1][0], pb1 = offp[di][1][1];
            float4 a0 = p1[pa0 & 0xffffu];
            float4 a1 = p1[pa0 >> 16];
            float4 a2 = p1[pa1 & 0xffffu];
            float4 a3 = p1[pa1 >> 16];
            float4 b0 = p2[pb0 & 0xffffu];
            float4 b1 = p2[pb0 >> 16];
            float4 b2 = p2[pb1 & 0xffffu];
            float4 b3 = p2[pb1 >> 16];

            u64 wA0 = pk2(wtf[di][0][0], wtf[di][0][0]);
            u64 wA1 = pk2(wtf[di][0][1], wtf[di][0][1]);
            u64 wA2 = pk2(wtf[di][0][2], wtf[di][0][2]);
            u64 wA3 = pk2(wtf[di][0][3], wtf[di][0][3]);
            u64 wB0 = pk2(wtf[di][1][0], wtf[di][1][0]);
            u64 wB1 = pk2(wtf[di][1][1], wtf[di][1][1]);
            u64 wB2 = pk2(wtf[di][1][2], wtf[di][1][2]);
            u64 wB3 = pk2(wtf[di][1][3], wtf[di][1][3]);

            u64 v01 = mul2_(wA0, pk2(a0.x, a0.y));
            v01 = fma2_(wA1, pk2(a1.x, a1.y), v01);
            v01 = fma2_(wA2, pk2(a2.x, a2.y), v01);
            v01 = fma2_(wA3, pk2(a3.x, a3.y), v01);
            u64 v23 = mul2_(wA0, pk2(a0.z, a0.w));
            v23 = fma2_(wA1, pk2(a1.z, a1.w), v23);
            v23 = fma2_(wA2, pk2(a2.z, a2.w), v23);
            v23 = fma2_(wA3, pk2(a3.z, a3.w), v23);
            u64 w01 = mul2_(wB0, pk2(b0.x, b0.y));
            w01 = fma2_(wB1, pk2(b1.x, b1.y), w01);
            w01 = fma2_(wB2, pk2(b2.x, b2.y), w01);
            w01 = fma2_(wB3, pk2(b3.x, b3.y), w01);
            u64 w23 = mul2_(wB0, pk2(b0.z, b0.w));
            w23 = fma2_(wB1, pk2(b1.z, b1.w), w23);
            w23 = fma2_(wB2, pk2(b2.z, b2.w), w23);
            w23 = fma2_(wB3, pk2(b3.z, b3.w), w23);

            // var = (q - s*(s/3)) / 3
            u64 s0 = add2_(add2_(r01, v01), w01);
            u64 q0 = fma2_(r01, r01, fma2_(v01, v01, mul2_(w01, w01)));
            u64 m0 = mul2_(s0, THIRD2);
            var[2 * q + 0][di] = mul2_(fma2_(m0 ^ NEG2MASK, s0, q0), THIRD2);

            u64 s1 = add2_(add2_(r23, v23), w23);
            u64 q1 = fma2_(r23, r23, fma2_(v23, v23, mul2_(w23, w23)));
            u64 m1 = mul2_(s1, THIRD2);
            var[2 * q + 1][di] = mul2_(fma2_(m1 ^ NEG2MASK, s1, q1), THIRD2);
        }
    }

    // Phase B: 27-tap contraction, weights from the constant bank (LDC).
    float umid0[9], umid1[9];
#pragma unroll
    for (int t = 0; t < 27; t++) {
        u64 acc0 = 0ULL, acc1 = 0ULL;
#pragma unroll
        for (int pp = 0; pp < 8; pp++) {
            ulonglong2 wl = c_sw[t * 8 + pp];
            acc0 = fma2_(var[2 * pp + 0][0], wl.x, acc0);
            acc0 = fma2_(var[2 * pp + 1][0], wl.y, acc0);
            acc1 = fma2_(var[2 * pp + 0][1], wl.x, acc1);
            acc1 = fma2_(var[2 * pp + 1][1], wl.y, acc1);
        }
        float u0 = hadd2(acc0), u1 = hadd2(acc1);
        int j = t / 3, dx = t - 3 * j;
        if (dx == 0)      su[j][x + 1] = pk2(u0, u1);
        else if (dx == 2) su[9 + j][x + 1] = pk2(u0, u1);
        else { umid0[j] = u0; umid1[j] = u1; }
    }
    __syncthreads();

    // fold dx: s(x) = u_dx0(x-1) + u_dx1(x) + u_dx2(x+1)
#pragma unroll
    for (int j = 0; j < 9; j++) {
        u64 sv = add2_(su[j][x], add2_(pk2(umid0[j], umid1[j]), su[9 + j][x + 2]));
        float s0, s1;
        unpk2(sv, s0, s1);
        g_s[(size_t)j * VOLc + idx0] = s0;
        g_s[(size_t)j * VOLc + idx1] = s1;
    }
}

// ---------------------------------------------------------------------------
// convfin: fused 9-tap conv + softmax + expected depth + confidence.
// Block = 512 threads = 32 consecutive pixels x 16 depth-slices (2 depths);
// 128B-coalesced lines, 2x warp parallelism vs r8; smem-tree reductions.
// ---------------------------------------------------------------------------
__global__ __launch_bounds__(512) void convfin_kernel(
    const float* __restrict__ depth_values,
    const float* __restrict__ breg,
    float* __restrict__ out)
{
    __shared__ float redA[16][33];
    __shared__ float redB[16][33];

    int p = threadIdx.x & 31;      // pixel within 32-chunk (lane)
    int slice = threadIdx.x >> 5;  // depth slice, 2 depths each
    int t = blockIdx.x * 32 + p;   // pixel over BHW
    int w = t & (Wc - 1);
    int h = (t / Wc) % Hc;
    int b = t / HWc;

    float acc[2];
    float bias = breg[0];
    acc[0] = bias; acc[1] = bias;

    int d0 = slice * 2;
#pragma unroll
    for (int dzi = 0; dzi < 3; dzi++) {
#pragma unroll
        for (int dyi = 0; dyi < 3; dyi++) {
            int yy = h + dyi - 1;
            if (yy < 0 || yy >= Hc) continue;   // uniform across block (same h)
            const float* sp = g_s + (size_t)(dzi * 3 + dyi) * VOLc +
                              ((size_t)b * Dc * Hc + yy) * Wc + w;
#pragma unroll
            for (int k = 0; k < 2; k++) {
                int zz = d0 + k + dzi - 1;
                if (zz >= 0 && zz < Dc)
                    acc[k] += sp[(size_t)zz * HWc];
            }
        }
    }

    // --- block reduction over the 16 slices, per pixel ---
    // 1) max
    float mx = fmaxf(acc[0], acc[1]);
    redA[slice][p] = mx;
    __syncthreads();
#pragma unroll
    for (int i = 0; i < 16; i++) mx = fmaxf(mx, redA[i][p]);
    __syncthreads();

    // 2) exp + sum
    float ssum = 0.f;
#pragma unroll
    for (int k = 0; k < 2; k++) {
        acc[k] = __expf(acc[k] - mx);
        ssum += acc[k];
    }
    redA[slice][p] = ssum;
    __syncthreads();
    float stot = 0.f;
#pragma unroll
    for (int i = 0; i < 16; i++) stot += redA[i][p];
    float inv = 1.f / stot;
    __syncthreads();

    // 3) expected depth + expected index
    int base = b * (Dc * HWc) + h * Wc + w;
    float depth = 0.f, ed = 0.f;
#pragma unroll
    for (int k = 0; k < 2; k++) {
        float pd = acc[k] * inv;
        acc[k] = pd;
        depth += pd * depth_values[base + (d0 + k) * HWc];
        ed += pd * (float)(d0 + k);
    }
    redA[slice][p] = depth;
    redB[slice][p] = ed;
    __syncthreads();
    float dtot = 0.f, edtot = 0.f;
#pragma unroll
    for (int i = 0; i < 16; i++) { dtot += redA[i][p]; edtot += redB[i][p]; }
    __syncthreads();

    // 4) confidence window
    int ix = min(max((int)edtot, 0), Dc - 1);
    float conf = 0.f;
#pragma unroll
    for (int k = 0; k < 2; k++) {
        int d = d0 + k;
        conf += (d >= ix - 1 && d <= ix + 2) ? acc[k] : 0.f;
    }
    redA[slice][p] = conf;
    __syncthreads();

    if (slice == 0) {
        float ctot = 0.f;
#pragma unroll
        for (int i = 0; i < 16; i++) ctot += redA[i][p];
        out[t] = dtot;
        out[BHWc + t] = ctot;
    }
}

// ---------------------------------------------------------------------------
extern "C" void kernel_launch(void* const* d_in, const int* in_sizes, int n_in,
                              void* d_out, int out_size)
{
    const float* features = nullptr;
    const float* projm = nullptr;
    const float* depthv = nullptr;
    const float* wreg = nullptr;
    const float* breg = nullptr;
    for (int i = 0; i < n_in; i++) {
        switch (in_sizes[i]) {
            case Bc * Vc * Cc * HWc: features = (const float*)d_in[i]; break;
            case VOLc:               depthv = (const float*)d_in[i]; break;
            case Bc * Vc * 2 * 16:   projm = (const float*)d_in[i]; break;
            case Cc * 27:            wreg = (const float*)d_in[i]; break;
            case 1:                  breg = (const float*)d_in[i]; break;
            default: break;
        }
    }
    float* out = (float*)d_out;

    void* swp_dev = nullptr;
    cudaGetSymbolAddress(&swp_dev, g_swp);  // symbol lookup only; no alloc/sync

    setup_kernel<<<1, 512>>>(projm, wreg);
    // D2D async copy into the constant bank (graph-capturable, allocation-free)
    cudaMemcpyToSymbolAsync(c_sw, swp_dev, sizeof(ulonglong2) * 27 * 8, 0,
                            cudaMemcpyDeviceToDevice, 0);
    repack_kernel<<<dim3(HWc / 32, Bc * Vc), dim3(32, 8)>>>(features);
    build_s_kernel<<<Bc * (Dc / 2) * Hc, Wc>>>(depthv);
    convfin_kernel<<<BHWc / 32, 512>>>(depthv, breg, out);
}

// round 15
// speedup vs baseline: 1.0518x; 1.0518x over previous
#include <cuda_runtime.h>
#include <math.h>

// Problem constants (fixed by the reference's setup_inputs)
#define Bc 2
#define Vc 3
#define Cc 32
#define Dc 32
#define Hc 96
#define Wc 128
#define HWc (Hc * Wc)            // 12288
#define VOLc (Bc * Dc * Hc * Wc) // 786432
#define BHWc (Bc * Hc * Wc)      // 24576
#define NSRC (Vc - 1)            // 2 source views
#define NG 8                     // channel groups of 4

typedef unsigned long long u64;

// Scratch (static device globals — no allocation)
__device__ float4 g_feat4[Bc * Vc * NG * HWc]; // channel-grouped features ~9.4MB
__device__ float g_s[9 * VOLc];                // x-folded 9-tap partials (~28 MB)
__device__ float g_xform[Bc * NSRC * 12];      // rot(9) + trans(3) per (b, src view)
__device__ ulonglong2 g_swp[27 * 8];           // packed weights staging (device)

// Constant bank: packed weights [tap][pair-pair] (3456 B)
__constant__ ulonglong2 c_sw[27 * 8];

// ---------------------------------------------------------------------------
// f32x2 packed helpers (Blackwell)
// ---------------------------------------------------------------------------
__device__ __forceinline__ u64 pk2(float a, float b) {
    u64 r; asm("mov.b64 %0, {%1,%2};" : "=l"(r) : "f"(a), "f"(b)); return r;
}
__device__ __forceinline__ u64 fma2_(u64 a, u64 b, u64 c) {
    u64 d; asm("fma.rn.f32x2 %0, %1, %2, %3;" : "=l"(d) : "l"(a), "l"(b), "l"(c)); return d;
}
__device__ __forceinline__ u64 mul2_(u64 a, u64 b) {
    u64 d; asm("mul.rn.f32x2 %0, %1, %2;" : "=l"(d) : "l"(a), "l"(b)); return d;
}
__device__ __forceinline__ u64 add2_(u64 a, u64 b) {
    u64 d; asm("add.rn.f32x2 %0, %1, %2;" : "=l"(d) : "l"(a), "l"(b)); return d;
}
__device__ __forceinline__ float hadd2(u64 a) {
    float x, y; asm("mov.b64 {%0,%1}, %2;" : "=f"(x), "=f"(y) : "l"(a)); return x + y;
}
__device__ __forceinline__ void unpk2(u64 a, float& x, float& y) {
    asm("mov.b64 {%0,%1}, %2;" : "=f"(x), "=f"(y) : "l"(a));
}
#define THIRD2 0x3EAAAAAB3EAAAAABULL
#define NEG2MASK 0x8000000080000000ULL

// ---------------------------------------------------------------------------
// Fused setup+prep: threads 0..3 compose/invert projections; threads 32..463
// pack the conv weights into the [tap][pair] f32x2 staging buffer.
// ---------------------------------------------------------------------------
__device__ void compose_mat(const float* pm, int b, int v, float P[16]) {
    const float* E = pm + (((b * Vc + v) * 2 + 0) * 16);
    const float* K = pm + (((b * Vc + v) * 2 + 1) * 16);
#pragma unroll
    for (int i = 0; i < 16; i++) P[i] = E[i];
#pragma unroll
    for (int i = 0; i < 3; i++)
#pragma unroll
        for (int j = 0; j < 4; j++)
            P[i * 4 + j] = K[i * 4 + 0] * E[0 * 4 + j] +
                           K[i * 4 + 1] * E[1 * 4 + j] +
                           K[i * 4 + 2] * E[2 * 4 + j];
}

__device__ void inv4(const float A[16], float R[16]) {
    float M[4][8];
    for (int i = 0; i < 4; i++) {
        for (int j = 0; j < 4; j++) {
            M[i][j] = A[i * 4 + j];
            M[i][4 + j] = (i == j) ? 1.f : 0.f;
        }
    }
    for (int col = 0; col < 4; col++) {
        int piv = col;
        float best = fabsf(M[col][col]);
        for (int r = col + 1; r < 4; r++) {
            float a = fabsf(M[r][col]);
            if (a > best) { best = a; piv = r; }
        }
        if (piv != col) {
            for (int j = 0; j < 8; j++) {
                float t = M[col][j]; M[col][j] = M[piv][j]; M[piv][j] = t;
            }
        }
        float p = 1.f / M[col][col];
        for (int j = 0; j < 8; j++) M[col][j] *= p;
        for (int r = 0; r < 4; r++) {
            if (r == col) continue;
            float f = M[r][col];
            for (int j = 0; j < 8; j++) M[r][j] -= f * M[col][j];
        }
    }
    for (int i = 0; i < 4; i++)
        for (int j = 0; j < 4; j++)
            R[i * 4 + j] = M[i][4 + j];
}

__global__ void setup_kernel(const float* __restrict__ pm,
                             const float* __restrict__ w_reg) {
    int tid = threadIdx.x;  // 512 threads
    if (tid < Bc * NSRC) {
        int t = tid;
        int b = t / NSRC;
        int v = (t % NSRC) + 1;
        float refP[16], srcP[16], invR[16], proj[16];
        compose_mat(pm, b, 0, refP);
        compose_mat(pm, b, v, srcP);
        inv4(refP, invR);
        for (int i = 0; i < 4; i++)
            for (int j = 0; j < 4; j++) {
                float s = 0.f;
                for (int k = 0; k < 4; k++) s += srcP[i * 4 + k] * invR[k * 4 + j];
                proj[i * 4 + j] = s;
            }
        float* X = g_xform + t * 12;
        X[0] = proj[0];  X[1] = proj[1];  X[2] = proj[2];
        X[3] = proj[4];  X[4] = proj[5];  X[5] = proj[6];
        X[6] = proj[8];  X[7] = proj[9];  X[8] = proj[10];
        X[9] = proj[3];  X[10] = proj[7]; X[11] = proj[11];
    }
    int i = tid - 32;  // weight packing on threads 32..463
    if (i >= 0 && i < 27 * 16) {
        int t = i >> 4, p = i & 15;
        u64* sw = (u64*)g_swp;
        sw[t * 16 + p] = pk2(w_reg[(2 * p) * 27 + t], w_reg[(2 * p + 1) * 27 + t]);
    }
}

// ---------------------------------------------------------------------------
// Repack features: (B,V,C,H,W) -> (B,V, C/4, H, W)[float4 over 4 channels]
// ---------------------------------------------------------------------------
__global__ __launch_bounds__(256) void repack_kernel(const float* __restrict__ feat) {
    __shared__ float tile[32][33];
    int bv = blockIdx.y;
    int pix0 = blockIdx.x * 32;
    int tx = threadIdx.x, ty = threadIdx.y; // 32 x 8
    const float* src = feat + (size_t)bv * Cc * HWc;
#pragma unroll
    for (int i = 0; i < 4; i++) {
        int c = ty + i * 8;
        tile[c][tx] = src[(size_t)c * HWc + pix0 + tx];
    }
    __syncthreads();
    float4 v;
    v.x = tile[4 * ty + 0][tx];
    v.y = tile[4 * ty + 1][tx];
    v.z = tile[4 * ty + 2][tx];
    v.w = tile[4 * ty + 3][tx];
    g_feat4[((size_t)bv * NG + ty) * HWc + pix0 + tx] = v;
}

// ---------------------------------------------------------------------------
// build_s: proven r13 version — trimmed regs, weights on the constant port.
// ---------------------------------------------------------------------------
__global__ __launch_bounds__(128, 4) void build_s_kernel(
    const float* __restrict__ depth_values)
{
    __shared__ u64 su[18][130];   // dx0 taps [0..8], dx2 taps [9..17], depth-pair packed

    int x = threadIdx.x;
    if (x < 18) { su[x][0] = 0ULL; su[x][129] = 0ULL; }
    __syncthreads();

    int row = blockIdx.x;                 // (b*(D/2) + d2)*H + h
    int h = row % Hc;
    int d2 = (row / Hc) & (Dc / 2 - 1);
    int b = row / (Hc * Dc / 2);
    int idx0 = ((b * Dc + 2 * d2) * Hc + h) * Wc + x;
    int idx1 = idx0 + HWc;

    float dep[2];
    dep[0] = depth_values[idx0];
    dep[1] = depth_values[idx1];

    // Warp coords per (depth, view): scalar weights + packed gather offsets
    float wtf[2][NSRC][4];
    unsigned int offp[2][NSRC][2]; // two 16-bit pixel offsets per reg
#pragma unroll
    for (int di = 0; di < 2; di++) {
#pragma unroll
        for (int s = 0; s < NSRC; s++) {
            const float* X = g_xform + (b * NSRC + s) * 12;
            float fx = (float)x, fy = (float)h;
            float Xx = (X[0] * fx + X[1] * fy + X[2]) * dep[di] + X[9];
            float Yy = (X[3] * fx + X[4] * fy + X[5]) * dep[di] + X[10];
            float Zz = (X[6] * fx + X[7] * fy + X[8]) * dep[di] + X[11];
            float iz = 1.f / Zz;
            float px = Xx * iz, py = Yy * iz;
            float x0 = floorf(px), y0 = floorf(py);
            float ax = px - x0, ay = py - y0;
            unsigned int o[4];
#pragma unroll
            for (int k = 0; k < 4; k++) {
                int dx = k & 1, dy = k >> 1;
                float xi = x0 + (float)dx, yi = y0 + (float)dy;
                float wg = (dx ? ax : 1.f - ax) * (dy ? ay : 1.f - ay);
                bool valid = (xi >= 0.f) && (xi <= (float)(Wc - 1)) &&
                             (yi >= 0.f) && (yi <= (float)(Hc - 1));
                wtf[di][s][k] = valid ? wg : 0.f;
                int xc = min(max((int)xi, 0), Wc - 1);
                int yc = min(max((int)yi, 0), Hc - 1);
                o[k] = (unsigned int)(yc * Wc + xc);
            }
            offp[di][s][0] = o[0] | (o[1] << 16);
            offp[di][s][1] = o[2] | (o[3] << 16);
        }
    }

    int pix = h * Wc + x;
    const float4* fr = g_feat4 + (size_t)(b * Vc + 0) * (NG * HWc) + pix;
    const float4* f1 = g_feat4 + (size_t)(b * Vc + 1) * (NG * HWc);
    const float4* f2 = g_feat4 + (size_t)(b * Vc + 2) * (NG * HWc);

    // Phase A: variance, channel-pair packed, per depth
    u64 var[16][2]; // [channel pair][depth]
#pragma unroll
    for (int q = 0; q < NG; q++) {
        float4 r4 = fr[q * HWc];
        u64 r01 = pk2(r4.x, r4.y), r23 = pk2(r4.z, r4.w);
        const float4* p1 = f1 + q * HWc;
        const float4* p2 = f2 + q * HWc;
#pragma unroll
        for (int di = 0; di < 2; di++) {
            unsigned int pa0 = offp[di][0][0], pa1 = offp[di][0][1];
            unsigned int pb0 = offp[di][1][0], pb1 = offp[di][1][1];
            float4 a0 = p1[pa0 & 0xffffu];
            float4 a1 = p1[pa0 >> 16];
            float4 a2 = p1[pa1 & 0xffffu];
            float4 a3 = p1[pa1 >> 16];
            float4 b0 = p2[pb0 & 0xffffu];
            float4 b1 = p2[pb0 >> 16];
            float4 b2 = p2[pb1 & 0xffffu];
            float4 b3 = p2[pb1 >> 16];

            u64 wA0 = pk2(wtf[di][0][0], wtf[di][0][0]);
            u64 wA1 = pk2(wtf[di][0][1], wtf[di][0][1]);
            u64 wA2 = pk2(wtf[di][0][2], wtf[di][0][2]);
            u64 wA3 = pk2(wtf[di][0][3], wtf[di][0][3]);
            u64 wB0 = pk2(wtf[di][1][0], wtf[di][1][0]);
            u64 wB1 = pk2(wtf[di][1][1], wtf[di][1][1]);
            u64 wB2 = pk2(wtf[di][1][2], wtf[di][1][2]);
            u64 wB3 = pk2(wtf[di][1][3], wtf[di][1][3]);

            u64 v01 = mul2_(wA0, pk2(a0.x, a0.y));
            v01 = fma2_(wA1, pk2(a1.x, a1.y), v01);
            v01 = fma2_(wA2, pk2(a2.x, a2.y), v01);
            v01 = fma2_(wA3, pk2(a3.x, a3.y), v01);
            u64 v23 = mul2_(wA0, pk2(a0.z, a0.w));
            v23 = fma2_(wA1, pk2(a1.z, a1.w), v23);
            v23 = fma2_(wA2, pk2(a2.z, a2.w), v23);
            v23 = fma2_(wA3, pk2(a3.z, a3.w), v23);
            u64 w01 = mul2_(wB0, pk2(b0.x, b0.y));
            w01 = fma2_(wB1, pk2(b1.x, b1.y), w01);
            w01 = fma2_(wB2, pk2(b2.x, b2.y), w01);
            w01 = fma2_(wB3, pk2(b3.x, b3.y), w01);
            u64 w23 = mul2_(wB0, pk2(b0.z, b0.w));
            w23 = fma2_(wB1, pk2(b1.z, b1.w), w23);
            w23 = fma2_(wB2, pk2(b2.z, b2.w), w23);
            w23 = fma2_(wB3, pk2(b3.z, b3.w), w23);

            // var = (q - s*(s/3)) / 3
            u64 s0 = add2_(add2_(r01, v01), w01);
            u64 q0 = fma2_(r01, r01, fma2_(v01, v01, mul2_(w01, w01)));
            u64 m0 = mul2_(s0, THIRD2);
            var[2 * q + 0][di] = mul2_(fma2_(m0 ^ NEG2MASK, s0, q0), THIRD2);

            u64 s1 = add2_(add2_(r23, v23), w23);
            u64 q1 = fma2_(r23, r23, fma2_(v23, v23, mul2_(w23, w23)));
            u64 m1 = mul2_(s1, THIRD2);
            var[2 * q + 1][di] = mul2_(fma2_(m1 ^ NEG2MASK, s1, q1), THIRD2);
        }
    }

    // Phase B: 27-tap contraction, weights from the constant bank (LDC).
    float umid0[9], umid1[9];
#pragma unroll
    for (int t = 0; t < 27; t++) {
        u64 acc0 = 0ULL, acc1 = 0ULL;
#pragma unroll
        for (int pp = 0; pp < 8; pp++) {
            ulonglong2 wl = c_sw[t * 8 + pp];
            acc0 = fma2_(var[2 * pp + 0][0], wl.x, acc0);
            acc0 = fma2_(var[2 * pp + 1][0], wl.y, acc0);
            acc1 = fma2_(var[2 * pp + 0][1], wl.x, acc1);
            acc1 = fma2_(var[2 * pp + 1][1], wl.y, acc1);
        }
        float u0 = hadd2(acc0), u1 = hadd2(acc1);
        int j = t / 3, dx = t - 3 * j;
        if (dx == 0)      su[j][x + 1] = pk2(u0, u1);
        else if (dx == 2) su[9 + j][x + 1] = pk2(u0, u1);
        else { umid0[j] = u0; umid1[j] = u1; }
    }
    __syncthreads();

    // fold dx: s(x) = u_dx0(x-1) + u_dx1(x) + u_dx2(x+1)
#pragma unroll
    for (int j = 0; j < 9; j++) {
        u64 sv = add2_(su[j][x], add2_(pk2(umid0[j], umid1[j]), su[9 + j][x + 2]));
        float s0, s1;
        unpk2(sv, s0, s1);
        g_s[(size_t)j * VOLc + idx0] = s0;
        g_s[(size_t)j * VOLc + idx1] = s1;
    }
}

// ---------------------------------------------------------------------------
// convfin: fused 9-tap conv + softmax + expected depth + confidence.
// Block = 32 consecutive pixels x 8 depth-slices (4 depths each); every
// global load is a fully-coalesced 128B line; cross-slice reduce via smem.
// (proven round-8 version, 11.6us)
// ---------------------------------------------------------------------------
__global__ __launch_bounds__(256) void convfin_kernel(
    const float* __restrict__ depth_values,
    const float* __restrict__ breg,
    float* __restrict__ out)
{
    __shared__ float redA[8][33];
    __shared__ float redB[8][33];

    int p = threadIdx.x & 31;      // pixel within 32-chunk (lane)
    int slice = threadIdx.x >> 5;  // depth slice, 4 depths each
    int t = blockIdx.x * 32 + p;   // pixel over BHW
    int w = t & (Wc - 1);
    int h = (t / Wc) % Hc;
    int b = t / HWc;

    float acc[4];
    float bias = breg[0];
#pragma unroll
    for (int k = 0; k < 4; k++) acc[k] = bias;

    int d0 = slice * 4;
#pragma unroll
    for (int dzi = 0; dzi < 3; dzi++) {
#pragma unroll
        for (int dyi = 0; dyi < 3; dyi++) {
            int yy = h + dyi - 1;
            if (yy < 0 || yy >= Hc) continue;   // uniform across block (same h)
            const float* sp = g_s + (size_t)(dzi * 3 + dyi) * VOLc +
                              ((size_t)b * Dc * Hc + yy) * Wc + w;
#pragma unroll
            for (int k = 0; k < 4; k++) {
                int zz = d0 + k + dzi - 1;
                if (zz >= 0 && zz < Dc)
                    acc[k] += sp[(size_t)zz * HWc];
            }
        }
    }

    // --- block reduction over the 8 slices, per pixel ---
    // 1) max
    float mx = fmaxf(fmaxf(acc[0], acc[1]), fmaxf(acc[2], acc[3]));
    redA[slice][p] = mx;
    __syncthreads();
#pragma unroll
    for (int i = 0; i < 8; i++) mx = fmaxf(mx, redA[i][p]);
    __syncthreads();

    // 2) exp + sum
    float ssum = 0.f;
#pragma unroll
    for (int k = 0; k < 4; k++) {
        acc[k] = __expf(acc[k] - mx);
        ssum += acc[k];
    }
    redA[slice][p] = ssum;
    __syncthreads();
    float stot = 0.f;
#pragma unroll
    for (int i = 0; i < 8; i++) stot += redA[i][p];
    float inv = 1.f / stot;
    __syncthreads();

    // 3) expected depth + expected index
    int base = b * (Dc * HWc) + h * Wc + w;
    float depth = 0.f, ed = 0.f;
#pragma unroll
    for (int k = 0; k < 4; k++) {
        float pd = acc[k] * inv;
        acc[k] = pd;
        depth += pd * depth_values[base + (d0 + k) * HWc];
        ed += pd * (float)(d0 + k);
    }
    redA[slice][p] = depth;
    redB[slice][p] = ed;
    __syncthreads();
    float dtot = 0.f, edtot = 0.f;
#pragma unroll
    for (int i = 0; i < 8; i++) { dtot += redA[i][p]; edtot += redB[i][p]; }
    __syncthreads();

    // 4) confidence window
    int ix = min(max((int)edtot, 0), Dc - 1);
    float conf = 0.f;
#pragma unroll
    for (int k = 0; k < 4; k++) {
        int d = d0 + k;
        conf += (d >= ix - 1 && d <= ix + 2) ? acc[k] : 0.f;
    }
    redA[slice][p] = conf;
    __syncthreads();

    if (slice == 0) {
        float ctot = 0.f;
#pragma unroll
        for (int i = 0; i < 8; i++) ctot += redA[i][p];
        out[t] = dtot;
        out[BHWc + t] = ctot;
    }
}

// ---------------------------------------------------------------------------
extern "C" void kernel_launch(void* const* d_in, const int* in_sizes, int n_in,
                              void* d_out, int out_size)
{
    const float* features = nullptr;
    const float* projm = nullptr;
    const float* depthv = nullptr;
    const float* wreg = nullptr;
    const float* breg = nullptr;
    for (int i = 0; i < n_in; i++) {
        switch (in_sizes[i]) {
            case Bc * Vc * Cc * HWc: features = (const float*)d_in[i]; break;
            case VOLc:               depthv = (const float*)d_in[i]; break;
            case Bc * Vc * 2 * 16:   projm = (const float*)d_in[i]; break;
            case Cc * 27:            wreg = (const float*)d_in[i]; break;
            case 1:                  breg = (const float*)d_in[i]; break;
            default: break;
        }
    }
    float* out = (float*)d_out;

    void* swp_dev = nullptr;
    cudaGetSymbolAddress(&swp_dev, g_swp);  // symbol lookup only; no alloc/sync

    setup_kernel<<<1, 512>>>(projm, wreg);
    // D2D async copy into the constant bank (graph-capturable, allocation-free)
    cudaMemcpyToSymbolAsync(c_sw, swp_dev, sizeof(ulonglong2) * 27 * 8, 0,
                            cudaMemcpyDeviceToDevice, 0);
    repack_kernel<<<dim3(HWc / 32, Bc * Vc), dim3(32, 8)>>>(features);
    build_s_kernel<<<Bc * (Dc / 2) * Hc, Wc>>>(depthv);
    convfin_kernel<<<BHWc / 32, 256>>>(depthv, breg, out);
}

// round 16
// speedup vs baseline: 1.0545x; 1.0025x over previous
#include <cuda_runtime.h>
#include <math.h>

// Problem constants (fixed by the reference's setup_inputs)
#define Bc 2
#define Vc 3
#define Cc 32
#define Dc 32
#define Hc 96
#define Wc 128
#define HWc (Hc * Wc)            // 12288
#define VOLc (Bc * Dc * Hc * Wc) // 786432
#define BHWc (Bc * Hc * Wc)      // 24576
#define NSRC (Vc - 1)            // 2 source views
#define NG 8                     // channel groups of 4

typedef unsigned long long u64;

// Scratch (static device globals — no allocation)
__device__ float4 g_feat4[Bc * Vc * NG * HWc]; // channel-grouped features ~9.4MB
__device__ float g_s[9 * VOLc];                // x-folded 9-tap partials (~28 MB)
__device__ float g_xform[Bc * NSRC * 12];      // rot(9) + trans(3) per (b, src view)
__device__ ulonglong2 g_swp[27 * 8];           // packed weights staging (device)

// Constant bank: packed weights [tap][pair-pair] (3456 B)
__constant__ ulonglong2 c_sw[27 * 8];

// ---------------------------------------------------------------------------
// f32x2 packed helpers (Blackwell)
// ---------------------------------------------------------------------------
__device__ __forceinline__ u64 pk2(float a, float b) {
    u64 r; asm("mov.b64 %0, {%1,%2};" : "=l"(r) : "f"(a), "f"(b)); return r;
}
__device__ __forceinline__ u64 fma2_(u64 a, u64 b, u64 c) {
    u64 d; asm("fma.rn.f32x2 %0, %1, %2, %3;" : "=l"(d) : "l"(a), "l"(b), "l"(c)); return d;
}
__device__ __forceinline__ u64 mul2_(u64 a, u64 b) {
    u64 d; asm("mul.rn.f32x2 %0, %1, %2;" : "=l"(d) : "l"(a), "l"(b)); return d;
}
__device__ __forceinline__ u64 add2_(u64 a, u64 b) {
    u64 d; asm("add.rn.f32x2 %0, %1, %2;" : "=l"(d) : "l"(a), "l"(b)); return d;
}
__device__ __forceinline__ float hadd2(u64 a) {
    float x, y; asm("mov.b64 {%0,%1}, %2;" : "=f"(x), "=f"(y) : "l"(a)); return x + y;
}
__device__ __forceinline__ void unpk2(u64 a, float& x, float& y) {
    asm("mov.b64 {%0,%1}, %2;" : "=f"(x), "=f"(y) : "l"(a));
}
#define THIRD2 0x3EAAAAAB3EAAAAABULL
#define NEG2MASK 0x8000000080000000ULL

// ---------------------------------------------------------------------------
// Projection composition / inversion (used by the fused repack+setup kernel)
// ---------------------------------------------------------------------------
__device__ void compose_mat(const float* pm, int b, int v, float P[16]) {
    const float* E = pm + (((b * Vc + v) * 2 + 0) * 16);
    const float* K = pm + (((b * Vc + v) * 2 + 1) * 16);
#pragma unroll
    for (int i = 0; i < 16; i++) P[i] = E[i];
#pragma unroll
    for (int i = 0; i < 3; i++)
#pragma unroll
        for (int j = 0; j < 4; j++)
            P[i * 4 + j] = K[i * 4 + 0] * E[0 * 4 + j] +
                           K[i * 4 + 1] * E[1 * 4 + j] +
                           K[i * 4 + 2] * E[2 * 4 + j];
}

__device__ void inv4(const float A[16], float R[16]) {
    float M[4][8];
    for (int i = 0; i < 4; i++) {
        for (int j = 0; j < 4; j++) {
            M[i][j] = A[i * 4 + j];
            M[i][4 + j] = (i == j) ? 1.f : 0.f;
        }
    }
    for (int col = 0; col < 4; col++) {
        int piv = col;
        float best = fabsf(M[col][col]);
        for (int r = col + 1; r < 4; r++) {
            float a = fabsf(M[r][col]);
            if (a > best) { best = a; piv = r; }
        }
        if (piv != col) {
            for (int j = 0; j < 8; j++) {
                float t = M[col][j]; M[col][j] = M[piv][j]; M[piv][j] = t;
            }
        }
        float p = 1.f / M[col][col];
        for (int j = 0; j < 8; j++) M[col][j] *= p;
        for (int r = 0; r < 4; r++) {
            if (r == col) continue;
            float f = M[r][col];
            for (int j = 0; j < 8; j++) M[r][j] -= f * M[col][j];
        }
    }
    for (int i = 0; i < 4; i++)
        for (int j = 0; j < 4; j++)
            R[i * 4 + j] = M[i][4 + j];
}

// ---------------------------------------------------------------------------
// Fused repack + setup: every block transposes its feature tile; block (0,0)
// additionally computes the projection transforms and packs the conv weights
// into the staging buffer for the constant-bank copy.
// ---------------------------------------------------------------------------
__global__ __launch_bounds__(256) void repack_kernel(
    const float* __restrict__ feat,
    const float* __restrict__ pm,
    const float* __restrict__ w_reg)
{
    __shared__ float tile[32][33];
    int bv = blockIdx.y;
    int pix0 = blockIdx.x * 32;
    int tx = threadIdx.x, ty = threadIdx.y; // 32 x 8
    const float* src = feat + (size_t)bv * Cc * HWc;
#pragma unroll
    for (int i = 0; i < 4; i++) {
        int c = ty + i * 8;
        tile[c][tx] = src[(size_t)c * HWc + pix0 + tx];
    }
    __syncthreads();
    float4 v;
    v.x = tile[4 * ty + 0][tx];
    v.y = tile[4 * ty + 1][tx];
    v.z = tile[4 * ty + 2][tx];
    v.w = tile[4 * ty + 3][tx];
    g_feat4[((size_t)bv * NG + ty) * HWc + pix0 + tx] = v;

    // --- setup work, block (0,0) only ---
    if (blockIdx.x == 0 && blockIdx.y == 0) {
        int tid = ty * 32 + tx;  // 0..255
        if (tid < Bc * NSRC) {
            int t = tid;
            int b = t / NSRC;
            int vv = (t % NSRC) + 1;
            float refP[16], srcP[16], invR[16], proj[16];
            compose_mat(pm, b, 0, refP);
            compose_mat(pm, b, vv, srcP);
            inv4(refP, invR);
            for (int i = 0; i < 4; i++)
                for (int j = 0; j < 4; j++) {
                    float s = 0.f;
                    for (int k = 0; k < 4; k++) s += srcP[i * 4 + k] * invR[k * 4 + j];
                    proj[i * 4 + j] = s;
                }
            float* X = g_xform + t * 12;
            X[0] = proj[0];  X[1] = proj[1];  X[2] = proj[2];
            X[3] = proj[4];  X[4] = proj[5];  X[5] = proj[6];
            X[6] = proj[8];  X[7] = proj[9];  X[8] = proj[10];
            X[9] = proj[3];  X[10] = proj[7]; X[11] = proj[11];
        }
        // weight packing: 432 items over 256 threads
        u64* sw = (u64*)g_swp;
        for (int i = tid; i < 27 * 16; i += 256) {
            int t = i >> 4, p = i & 15;
            sw[t * 16 + p] = pk2(w_reg[(2 * p) * 27 + t], w_reg[(2 * p + 1) * 27 + t]);
        }
    }
}

// ---------------------------------------------------------------------------
// build_s: proven r13 version — trimmed regs, weights on the constant port.
// ---------------------------------------------------------------------------
__global__ __launch_bounds__(128, 4) void build_s_kernel(
    const float* __restrict__ depth_values)
{
    __shared__ u64 su[18][130];   // dx0 taps [0..8], dx2 taps [9..17], depth-pair packed

    int x = threadIdx.x;
    if (x < 18) { su[x][0] = 0ULL; su[x][129] = 0ULL; }
    __syncthreads();

    int row = blockIdx.x;                 // (b*(D/2) + d2)*H + h
    int h = row % Hc;
    int d2 = (row / Hc) & (Dc / 2 - 1);
    int b = row / (Hc * Dc / 2);
    int idx0 = ((b * Dc + 2 * d2) * Hc + h) * Wc + x;
    int idx1 = idx0 + HWc;

    float dep[2];
    dep[0] = depth_values[idx0];
    dep[1] = depth_values[idx1];

    // Warp coords per (depth, view): scalar weights + packed gather offsets
    float wtf[2][NSRC][4];
    unsigned int offp[2][NSRC][2]; // two 16-bit pixel offsets per reg
#pragma unroll
    for (int di = 0; di < 2; di++) {
#pragma unroll
        for (int s = 0; s < NSRC; s++) {
            const float* X = g_xform + (b * NSRC + s) * 12;
            float fx = (float)x, fy = (float)h;
            float Xx = (X[0] * fx + X[1] * fy + X[2]) * dep[di] + X[9];
            float Yy = (X[3] * fx + X[4] * fy + X[5]) * dep[di] + X[10];
            float Zz = (X[6] * fx + X[7] * fy + X[8]) * dep[di] + X[11];
            float iz = 1.f / Zz;
            float px = Xx * iz, py = Yy * iz;
            float x0 = floorf(px), y0 = floorf(py);
            float ax = px - x0, ay = py - y0;
            unsigned int o[4];
#pragma unroll
            for (int k = 0; k < 4; k++) {
                int dx = k & 1, dy = k >> 1;
                float xi = x0 + (float)dx, yi = y0 + (float)dy;
                float wg = (dx ? ax : 1.f - ax) * (dy ? ay : 1.f - ay);
                bool valid = (xi >= 0.f) && (xi <= (float)(Wc - 1)) &&
                             (yi >= 0.f) && (yi <= (float)(Hc - 1));
                wtf[di][s][k] = valid ? wg : 0.f;
                int xc = min(max((int)xi, 0), Wc - 1);
                int yc = min(max((int)yi, 0), Hc - 1);
                o[k] = (unsigned int)(yc * Wc + xc);
            }
            offp[di][s][0] = o[0] | (o[1] << 16);
            offp[di][s][1] = o[2] | (o[3] << 16);
        }
    }

    int pix = h * Wc + x;
    const float4* fr = g_feat4 + (size_t)(b * Vc + 0) * (NG * HWc) + pix;
    const float4* f1 = g_feat4 + (size_t)(b * Vc + 1) * (NG * HWc);
    const float4* f2 = g_feat4 + (size_t)(b * Vc + 2) * (NG * HWc);

    // Phase A: variance, channel-pair packed, per depth
    u64 var[16][2]; // [channel pair][depth]
#pragma unroll
    for (int q = 0; q < NG; q++) {
        float4 r4 = fr[q * HWc];
        u64 r01 = pk2(r4.x, r4.y), r23 = pk2(r4.z, r4.w);
        const float4* p1 = f1 + q * HWc;
        const float4* p2 = f2 + q * HWc;
#pragma unroll
        for (int di = 0; di < 2; di++) {
            unsigned int pa0 = offp[di][0][0], pa1 = offp[di][0][1];
            unsigned int pb0 = offp[di][1][0], pb1 = offp[di][1][1];
            float4 a0 = p1[pa0 & 0xffffu];
            float4 a1 = p1[pa0 >> 16];
            float4 a2 = p1[pa1 & 0xffffu];
            float4 a3 = p1[pa1 >> 16];
            float4 b0 = p2[pb0 & 0xffffu];
            float4 b1 = p2[pb0 >> 16];
            float4 b2 = p2[pb1 & 0xffffu];
            float4 b3 = p2[pb1 >> 16];

            u64 wA0 = pk2(wtf[di][0][0], wtf[di][0][0]);
            u64 wA1 = pk2(wtf[di][0][1], wtf[di][0][1]);
            u64 wA2 = pk2(wtf[di][0][2], wtf[di][0][2]);
            u64 wA3 = pk2(wtf[di][0][3], wtf[di][0][3]);
            u64 wB0 = pk2(wtf[di][1][0], wtf[di][1][0]);
            u64 wB1 = pk2(wtf[di][1][1], wtf[di][1][1]);
            u64 wB2 = pk2(wtf[di][1][2], wtf[di][1][2]);
            u64 wB3 = pk2(wtf[di][1][3], wtf[di][1][3]);

            u64 v01 = mul2_(wA0, pk2(a0.x, a0.y));
            v01 = fma2_(wA1, pk2(a1.x, a1.y), v01);
            v01 = fma2_(wA2, pk2(a2.x, a2.y), v01);
            v01 = fma2_(wA3, pk2(a3.x, a3.y), v01);
            u64 v23 = mul2_(wA0, pk2(a0.z, a0.w));
            v23 = fma2_(wA1, pk2(a1.z, a1.w), v23);
            v23 = fma2_(wA2, pk2(a2.z, a2.w), v23);
            v23 = fma2_(wA3, pk2(a3.z, a3.w), v23);
            u64 w01 = mul2_(wB0, pk2(b0.x, b0.y));
            w01 = fma2_(wB1, pk2(b1.x, b1.y), w01);
            w01 = fma2_(wB2, pk2(b2.x, b2.y), w01);
            w01 = fma2_(wB3, pk2(b3.x, b3.y), w01);
            u64 w23 = mul2_(wB0, pk2(b0.z, b0.w));
            w23 = fma2_(wB1, pk2(b1.z, b1.w), w23);
            w23 = fma2_(wB2, pk2(b2.z, b2.w), w23);
            w23 = fma2_(wB3, pk2(b3.z, b3.w), w23);

            // var = (q - s*(s/3)) / 3
            u64 s0 = add2_(add2_(r01, v01), w01);
            u64 q0 = fma2_(r01, r01, fma2_(v01, v01, mul2_(w01, w01)));
            u64 m0 = mul2_(s0, THIRD2);
            var[2 * q + 0][di] = mul2_(fma2_(m0 ^ NEG2MASK, s0, q0), THIRD2);

            u64 s1 = add2_(add2_(r23, v23), w23);
            u64 q1 = fma2_(r23, r23, fma2_(v23, v23, mul2_(w23, w23)));
            u64 m1 = mul2_(s1, THIRD2);
            var[2 * q + 1][di] = mul2_(fma2_(m1 ^ NEG2MASK, s1, q1), THIRD2);
        }
    }

    // Phase B: 27-tap contraction, weights from the constant bank (LDC).
    float umid0[9], umid1[9];
#pragma unroll
    for (int t = 0; t < 27; t++) {
        u64 acc0 = 0ULL, acc1 = 0ULL;
#pragma unroll
        for (int pp = 0; pp < 8; pp++) {
            ulonglong2 wl = c_sw[t * 8 + pp];
            acc0 = fma2_(var[2 * pp + 0][0], wl.x, acc0);
            acc0 = fma2_(var[2 * pp + 1][0], wl.y, acc0);
            acc1 = fma2_(var[2 * pp + 0][1], wl.x, acc1);
            acc1 = fma2_(var[2 * pp + 1][1], wl.y, acc1);
        }
        float u0 = hadd2(acc0), u1 = hadd2(acc1);
        int j = t / 3, dx = t - 3 * j;
        if (dx == 0)      su[j][x + 1] = pk2(u0, u1);
        else if (dx == 2) su[9 + j][x + 1] = pk2(u0, u1);
        else { umid0[j] = u0; umid1[j] = u1; }
    }
    __syncthreads();

    // fold dx: s(x) = u_dx0(x-1) + u_dx1(x) + u_dx2(x+1)
#pragma unroll
    for (int j = 0; j < 9; j++) {
        u64 sv = add2_(su[j][x], add2_(pk2(umid0[j], umid1[j]), su[9 + j][x + 2]));
        float s0, s1;
        unpk2(sv, s0, s1);
        g_s[(size_t)j * VOLc + idx0] = s0;
        g_s[(size_t)j * VOLc + idx1] = s1;
    }
}

// ---------------------------------------------------------------------------
// convfin: fused 9-tap conv + softmax + expected depth + confidence.
// Block = 32 consecutive pixels x 8 depth-slices (4 depths each); every
// global load is a fully-coalesced 128B line; cross-slice reduce via smem.
// (proven round-8 version)
// ---------------------------------------------------------------------------
__global__ __launch_bounds__(256) void convfin_kernel(
    const float* __restrict__ depth_values,
    const float* __restrict__ breg,
    float* __restrict__ out)
{
    __shared__ float redA[8][33];
    __shared__ float redB[8][33];

    int p = threadIdx.x & 31;      // pixel within 32-chunk (lane)
    int slice = threadIdx.x >> 5;  // depth slice, 4 depths each
    int t = blockIdx.x * 32 + p;   // pixel over BHW
    int w = t & (Wc - 1);
    int h = (t / Wc) % Hc;
    int b = t / HWc;

    float acc[4];
    float bias = breg[0];
#pragma unroll
    for (int k = 0; k < 4; k++) acc[k] = bias;

    int d0 = slice * 4;
#pragma unroll
    for (int dzi = 0; dzi < 3; dzi++) {
#pragma unroll
        for (int dyi = 0; dyi < 3; dyi++) {
            int yy = h + dyi - 1;
            if (yy < 0 || yy >= Hc) continue;   // uniform across block (same h)
            const float* sp = g_s + (size_t)(dzi * 3 + dyi) * VOLc +
                              ((size_t)b * Dc * Hc + yy) * Wc + w;
#pragma unroll
            for (int k = 0; k < 4; k++) {
                int zz = d0 + k + dzi - 1;
                if (zz >= 0 && zz < Dc)
                    acc[k] += sp[(size_t)zz * HWc];
            }
        }
    }

    // --- block reduction over the 8 slices, per pixel ---
    // 1) max
    float mx = fmaxf(fmaxf(acc[0], acc[1]), fmaxf(acc[2], acc[3]));
    redA[slice][p] = mx;
    __syncthreads();
#pragma unroll
    for (int i = 0; i < 8; i++) mx = fmaxf(mx, redA[i][p]);
    __syncthreads();

    // 2) exp + sum
    float ssum = 0.f;
#pragma unroll
    for (int k = 0; k < 4; k++) {
        acc[k] = __expf(acc[k] - mx);
        ssum += acc[k];
    }
    redA[slice][p] = ssum;
    __syncthreads();
    float stot = 0.f;
#pragma unroll
    for (int i = 0; i < 8; i++) stot += redA[i][p];
    float inv = 1.f / stot;
    __syncthreads();

    // 3) expected depth + expected index
    int base = b * (Dc * HWc) + h * Wc + w;
    float depth = 0.f, ed = 0.f;
#pragma unroll
    for (int k = 0; k < 4; k++) {
        float pd = acc[k] * inv;
        acc[k] = pd;
        depth += pd * depth_values[base + (d0 + k) * HWc];
        ed += pd * (float)(d0 + k);
    }
    redA[slice][p] = depth;
    redB[slice][p] = ed;
    __syncthreads();
    float dtot = 0.f, edtot = 0.f;
#pragma unroll
    for (int i = 0; i < 8; i++) { dtot += redA[i][p]; edtot += redB[i][p]; }
    __syncthreads();

    // 4) confidence window
    int ix = min(max((int)edtot, 0), Dc - 1);
    float conf = 0.f;
#pragma unroll
    for (int k = 0; k < 4; k++) {
        int d = d0 + k;
        conf += (d >= ix - 1 && d <= ix + 2) ? acc[k] : 0.f;
    }
    redA[slice][p] = conf;
    __syncthreads();

    if (slice == 0) {
        float ctot = 0.f;
#pragma unroll
        for (int i = 0; i < 8; i++) ctot += redA[i][p];
        out[t] = dtot;
        out[BHWc + t] = ctot;
    }
}

// ---------------------------------------------------------------------------
extern "C" void kernel_launch(void* const* d_in, const int* in_sizes, int n_in,
                              void* d_out, int out_size)
{
    const float* features = nullptr;
    const float* projm = nullptr;
    const float* depthv = nullptr;
    const float* wreg = nullptr;
    const float* breg = nullptr;
    for (int i = 0; i < n_in; i++) {
        switch (in_sizes[i]) {
            case Bc * Vc * Cc * HWc: features = (const float*)d_in[i]; break;
            case VOLc:               depthv = (const float*)d_in[i]; break;
            case Bc * Vc * 2 * 16:   projm = (const float*)d_in[i]; break;
            case Cc * 27:            wreg = (const float*)d_in[i]; break;
            case 1:                  breg = (const float*)d_in[i]; break;
            default: break;
        }
    }
    float* out = (float*)d_out;

    void* swp_dev = nullptr;
    cudaGetSymbolAddress(&swp_dev, g_swp);  // symbol lookup only; no alloc/sync

    // repack also performs projection setup + weight packing (block 0,0)
    repack_kernel<<<dim3(HWc / 32, Bc * Vc), dim3(32, 8)>>>(features, projm, wreg);
    // D2D async copy into the constant bank (graph-capturable, allocation-free)
    cudaMemcpyToSymbolAsync(c_sw, swp_dev, sizeof(ulonglong2) * 27 * 8, 0,
                            cudaMemcpyDeviceToDevice, 0);
    build_s_kernel<<<Bc * (Dc / 2) * Hc, Wc>>>(depthv);
    convfin_kernel<<<BHWc / 32, 256>>>(depthv, breg, out);
}